// round 1
// baseline (speedup 1.0000x reference)
#include <cuda_runtime.h>
#include <math.h>

#define Bn 2
#define Nn 1024
#define Dn 64
#define SCHUNKS 8      // s-dimension split for msg_agg
#define TT 32          // t-tile per block in msg_agg
#define SC (Nn / SCHUNKS)  // 128 s per block

// -------- scratch (no malloc allowed) --------
__device__ float g_proj[Bn * Nn * Dn];
__device__ float g_ps[Bn * Nn * Dn];                // proj @ W1[:D]
__device__ float g_ptb[Bn * Nn * Dn];               // proj @ W1[D:] + b1 (b1 folded)
__device__ float g_hpart[SCHUNKS * Bn * Nn * Dn];   // partial weighted relu sums

// ============================================================
// Kernel 1: A = softmax((mask_diag(edge_logits) + gumbel(u)) / tau)
// one block per row t, 256 threads, 4 elems/thread
// ============================================================
__global__ void __launch_bounds__(256) gumbel_softmax_kernel(
    const float* __restrict__ u, const float* __restrict__ el,
    float* __restrict__ A)
{
    int t = blockIdx.x;
    int tid = threadIdx.x;
    const float* ur = u + t * Nn;
    const float* er = el + t * Nn;

    float v[4];
    float mx = -3.4e38f;
#pragma unroll
    for (int i = 0; i < 4; i++) {
        int s = tid + i * 256;
        float g = -logf(-logf(ur[s] + 1e-9f) + 1e-9f);
        float m = (s == t) ? -1e9f : er[s];
        float L = (m + g) * 2.0f;   // / tau, tau = 0.5
        v[i] = L;
        mx = fmaxf(mx, L);
    }

    __shared__ float redm[8];
    __shared__ float reds[8];
#pragma unroll
    for (int o = 16; o; o >>= 1) mx = fmaxf(mx, __shfl_xor_sync(0xffffffffu, mx, o));
    if ((tid & 31) == 0) redm[tid >> 5] = mx;
    __syncthreads();
    float bm = redm[0];
#pragma unroll
    for (int i = 1; i < 8; i++) bm = fmaxf(bm, redm[i]);

    float sum = 0.f;
#pragma unroll
    for (int i = 0; i < 4; i++) { v[i] = expf(v[i] - bm); sum += v[i]; }
#pragma unroll
    for (int o = 16; o; o >>= 1) sum += __shfl_xor_sync(0xffffffffu, sum, o);
    if ((tid & 31) == 0) reds[tid >> 5] = sum;
    __syncthreads();
    float bs = reds[0];
#pragma unroll
    for (int i = 1; i < 8; i++) bs += reds[i];
    float inv = 1.0f / bs;

#pragma unroll
    for (int i = 0; i < 4; i++)
        A[t * Nn + tid + i * 256] = v[i] * inv;
}

// ============================================================
// Kernel 2: proj = entity_states @ W_proj + b_proj   (16 rows / block)
// ============================================================
__global__ void __launch_bounds__(256) proj_kernel(
    const float* __restrict__ es, const float* __restrict__ Wp,
    const float* __restrict__ bp)
{
    __shared__ float sW[64 * 64];
    __shared__ float sE[16 * 64];
    int tid = threadIdx.x;
    int row0 = blockIdx.x * 16;
    for (int i = tid; i < 4096; i += 256) sW[i] = Wp[i];
    for (int i = tid; i < 1024; i += 256) sE[i] = es[row0 * 64 + i];
    __syncthreads();

    int r = tid >> 4;
    int q = (tid & 15) << 2;
    float4 acc = *(const float4*)(bp + q);
    const float* er = sE + r * 64;
#pragma unroll
    for (int k = 0; k < 64; k++) {
        float e = er[k];
        float4 w = *(const float4*)(sW + k * 64 + q);
        acc.x = fmaf(e, w.x, acc.x);
        acc.y = fmaf(e, w.y, acc.y);
        acc.z = fmaf(e, w.z, acc.z);
        acc.w = fmaf(e, w.w, acc.w);
    }
    *(float4*)(g_proj + (row0 + r) * 64 + q) = acc;
}

// ============================================================
// Kernel 3: ps = proj @ W1[:D],  ptb = proj @ W1[D:] + b1
// ============================================================
__global__ void __launch_bounds__(256) pspt_kernel(
    const float* __restrict__ W1, const float* __restrict__ b1)
{
    __shared__ float sW[128 * 64];  // 32 KB
    __shared__ float sP[16 * 64];
    int tid = threadIdx.x;
    int row0 = blockIdx.x * 16;
    for (int i = tid; i < 8192; i += 256) sW[i] = W1[i];
    for (int i = tid; i < 1024; i += 256) sP[i] = g_proj[row0 * 64 + i];
    __syncthreads();

    int r = tid >> 4;
    int q = (tid & 15) << 2;
    float4 aps = make_float4(0.f, 0.f, 0.f, 0.f);
    float4 apt = *(const float4*)(b1 + q);
    const float* pr = sP + r * 64;
#pragma unroll
    for (int k = 0; k < 64; k++) {
        float p = pr[k];
        float4 wa = *(const float4*)(sW + k * 64 + q);
        float4 wb = *(const float4*)(sW + (64 + k) * 64 + q);
        aps.x = fmaf(p, wa.x, aps.x);
        aps.y = fmaf(p, wa.y, aps.y);
        aps.z = fmaf(p, wa.z, aps.z);
        aps.w = fmaf(p, wa.w, aps.w);
        apt.x = fmaf(p, wb.x, apt.x);
        apt.y = fmaf(p, wb.y, apt.y);
        apt.z = fmaf(p, wb.z, apt.z);
        apt.w = fmaf(p, wb.w, apt.w);
    }
    *(float4*)(g_ps  + (row0 + r) * 64 + q) = aps;
    *(float4*)(g_ptb + (row0 + r) * 64 + q) = apt;
}

// ============================================================
// Kernel 4 (hot): hbar_part[c,b,t,:] = sum_{s in chunk c} A[t,s] *
//                 relu(ps[b,s,:] + ptb[b,t,:])
// grid (SCHUNKS, N/TT, B), 256 threads:
//   thread = (tg = tid/16 handling 2 t's, dq = tid%16 handling 4 d's)
// ============================================================
__global__ void __launch_bounds__(256) msg_agg_kernel(const float* __restrict__ A)
{
    __shared__ float sP[SC * 64];   // 32 KB ps tile
    __shared__ float sA[TT * SC];   // 16 KB A tile, [t_local][s_local]
    int b  = blockIdx.z;
    int t0 = blockIdx.y * TT;
    int s0 = blockIdx.x * SC;
    int tid = threadIdx.x;

    {
        const float4* gp = (const float4*)(g_ps + (b * Nn + s0) * Dn);
        float4* sp4 = (float4*)sP;
#pragma unroll
        for (int i = 0; i < (SC * 16) / 256; i++)
            sp4[tid + i * 256] = gp[tid + i * 256];
        for (int i = tid; i < TT * SC; i += 256) {
            int tl = i >> 7;        // / SC
            int sl = i & (SC - 1);
            sA[i] = A[(t0 + tl) * Nn + s0 + sl];
        }
    }
    __syncthreads();

    int q  = (tid & 15) << 2;
    int tg = tid >> 4;
    int ta = t0 + tg * 2;
    float4 c0 = *(const float4*)(g_ptb + (b * Nn + ta) * Dn + q);
    float4 c1 = *(const float4*)(g_ptb + (b * Nn + ta + 1) * Dn + q);
    float4 acc0 = make_float4(0.f, 0.f, 0.f, 0.f);
    float4 acc1 = make_float4(0.f, 0.f, 0.f, 0.f);
    const float4* p4 = ((const float4*)sP) + (q >> 2);
    const float* a0 = sA + (tg * 2) * SC;
    const float* a1 = a0 + SC;

#pragma unroll 4
    for (int s = 0; s < SC; s++) {
        float4 p = p4[s * 16];
        float aa = a0[s];
        float ab = a1[s];
        float x;
        x = fmaxf(p.x + c0.x, 0.f); acc0.x = fmaf(aa, x, acc0.x);
        x = fmaxf(p.y + c0.y, 0.f); acc0.y = fmaf(aa, x, acc0.y);
        x = fmaxf(p.z + c0.z, 0.f); acc0.z = fmaf(aa, x, acc0.z);
        x = fmaxf(p.w + c0.w, 0.f); acc0.w = fmaf(aa, x, acc0.w);
        x = fmaxf(p.x + c1.x, 0.f); acc1.x = fmaf(ab, x, acc1.x);
        x = fmaxf(p.y + c1.y, 0.f); acc1.y = fmaf(ab, x, acc1.y);
        x = fmaxf(p.z + c1.z, 0.f); acc1.z = fmaf(ab, x, acc1.z);
        x = fmaxf(p.w + c1.w, 0.f); acc1.w = fmaf(ab, x, acc1.w);
    }

    int c = blockIdx.x;
    float* hp = g_hpart + (size_t)(c * Bn + b) * Nn * Dn;
    *(float4*)(hp + (ta) * Dn + q)     = acc0;
    *(float4*)(hp + (ta + 1) * Dn + q) = acc1;
}

// ============================================================
// Kernel 5: hbar = sum_c hpart;  next_state = es + hbar @ W2 + b2
// ============================================================
__global__ void __launch_bounds__(256) out_kernel(
    const float* __restrict__ es, const float* __restrict__ W2,
    const float* __restrict__ b2, float* __restrict__ ns)
{
    __shared__ float sW[64 * 64];
    __shared__ float sH[16 * 64];
    int tid = threadIdx.x;
    int row0 = blockIdx.x * 16;
    for (int i = tid; i < 4096; i += 256) sW[i] = W2[i];
    for (int i = tid; i < 1024; i += 256) {
        int gr = row0 + (i >> 6);
        int d  = i & 63;
        float h = 0.f;
#pragma unroll
        for (int c = 0; c < SCHUNKS; c++)
            h += g_hpart[((size_t)c * Bn * Nn + gr) * Dn + d];
        sH[i] = h;
    }
    __syncthreads();

    int r = tid >> 4;
    int q = (tid & 15) << 2;
    float4 acc = *(const float4*)(b2 + q);
    const float* hr = sH + r * 64;
#pragma unroll
    for (int k = 0; k < 64; k++) {
        float h = hr[k];
        float4 w = *(const float4*)(sW + k * 64 + q);
        acc.x = fmaf(h, w.x, acc.x);
        acc.y = fmaf(h, w.y, acc.y);
        acc.z = fmaf(h, w.z, acc.z);
        acc.w = fmaf(h, w.w, acc.w);
    }
    float4 e = *(const float4*)(es + (row0 + r) * 64 + q);
    acc.x += e.x; acc.y += e.y; acc.z += e.z; acc.w += e.w;
    *(float4*)(ns + (row0 + r) * 64 + q) = acc;
}

// ============================================================
extern "C" void kernel_launch(void* const* d_in, const int* in_sizes, int n_in,
                              void* d_out, int out_size)
{
    const float* es = (const float*)d_in[0];
    const float* u  = (const float*)d_in[1];
    const float* Wp = (const float*)d_in[2];
    const float* bp = (const float*)d_in[3];
    const float* el = (const float*)d_in[4];
    const float* W1 = (const float*)d_in[5];
    const float* b1 = (const float*)d_in[6];
    const float* W2 = (const float*)d_in[7];
    const float* b2 = (const float*)d_in[8];

    float* outNS = (float*)d_out;                 // next_state [B,N,D]
    float* outA  = outNS + Bn * Nn * Dn;          // A [N,N]

    gumbel_softmax_kernel<<<Nn, 256>>>(u, el, outA);
    proj_kernel<<<(Bn * Nn) / 16, 256>>>(es, Wp, bp);
    pspt_kernel<<<(Bn * Nn) / 16, 256>>>(W1, b1);
    msg_agg_kernel<<<dim3(SCHUNKS, Nn / TT, Bn), 256>>>(outA);
    out_kernel<<<(Bn * Nn) / 16, 256>>>(es, W2, b2, outNS);
}

// round 2
// speedup vs baseline: 1.1965x; 1.1965x over previous
#include <cuda_runtime.h>
#include <math.h>

#define Bn 2
#define Nn 1024
#define Dn 64
#define SCHUNKS 16          // s-dimension split for msg_agg
#define TT 32               // t-tile per block in msg_agg
#define SC (Nn / SCHUNKS)   // 64 s per block

typedef unsigned long long u64t;

// -------- scratch (no malloc allowed) --------
__device__ float g_ps[Bn * Nn * Dn];                // es @ Wf[:, :64] + bf[:64]
__device__ float g_ptb[Bn * Nn * Dn];               // es @ Wf[:, 64:] + bf[64:]
__device__ float g_Wf[Dn * 2 * Dn];                 // [64][128] fused Wp@W1
__device__ float g_bf[2 * Dn];                      // fused bias
__device__ float g_hpart[SCHUNKS * Bn * Nn * Dn];   // partial weighted relu sums

// ---------- packed f32x2 helpers ----------
__device__ __forceinline__ u64t pack2(float lo, float hi) {
    u64t r;
    asm("mov.b64 %0, {%1, %2};" : "=l"(r) : "f"(lo), "f"(hi));
    return r;
}
__device__ __forceinline__ void unpack2(u64t v, float& lo, float& hi) {
    asm("mov.b64 {%0, %1}, %2;" : "=f"(lo), "=f"(hi) : "l"(v));
}
__device__ __forceinline__ u64t add2(u64t a, u64t b) {
    u64t d;
    asm("add.rn.f32x2 %0, %1, %2;" : "=l"(d) : "l"(a), "l"(b));
    return d;
}
__device__ __forceinline__ u64t fma2(u64t a, u64t b, u64t c) {
    u64t d;
    asm("fma.rn.f32x2 %0, %1, %2, %3;" : "=l"(d) : "l"(a), "l"(b), "l"(c));
    return d;
}
__device__ __forceinline__ u64t relu2(u64t x) {
    u64t r;
    asm("{\n\t"
        ".reg .f32 lo, hi;\n\t"
        "mov.b64 {lo, hi}, %1;\n\t"
        "max.f32 lo, lo, 0f00000000;\n\t"
        "max.f32 hi, hi, 0f00000000;\n\t"
        "mov.b64 %0, {lo, hi};\n\t"
        "}" : "=l"(r) : "l"(x));
    return r;
}

// ============================================================
// Kernel 1: A = softmax((mask_diag(edge_logits) + gumbel(u)) / tau)
// ============================================================
__global__ void __launch_bounds__(256) gumbel_softmax_kernel(
    const float* __restrict__ u, const float* __restrict__ el,
    float* __restrict__ A)
{
    int t = blockIdx.x;
    int tid = threadIdx.x;
    const float* ur = u + t * Nn;
    const float* er = el + t * Nn;

    float v[4];
    float mx = -3.4e38f;
#pragma unroll
    for (int i = 0; i < 4; i++) {
        int s = tid + i * 256;
        float g = -__logf(-__logf(ur[s] + 1e-9f) + 1e-9f);
        float m = (s == t) ? -1e9f : er[s];
        float L = (m + g) * 2.0f;   // / tau, tau = 0.5
        v[i] = L;
        mx = fmaxf(mx, L);
    }

    __shared__ float redm[8];
    __shared__ float reds[8];
#pragma unroll
    for (int o = 16; o; o >>= 1) mx = fmaxf(mx, __shfl_xor_sync(0xffffffffu, mx, o));
    if ((tid & 31) == 0) redm[tid >> 5] = mx;
    __syncthreads();
    float bm = redm[0];
#pragma unroll
    for (int i = 1; i < 8; i++) bm = fmaxf(bm, redm[i]);

    float sum = 0.f;
#pragma unroll
    for (int i = 0; i < 4; i++) { v[i] = __expf(v[i] - bm); sum += v[i]; }
#pragma unroll
    for (int o = 16; o; o >>= 1) sum += __shfl_xor_sync(0xffffffffu, sum, o);
    if ((tid & 31) == 0) reds[tid >> 5] = sum;
    __syncthreads();
    float bs = reds[0];
#pragma unroll
    for (int i = 1; i < 8; i++) bs += reds[i];
    float inv = 1.0f / bs;

#pragma unroll
    for (int i = 0; i < 4; i++)
        A[t * Nn + tid + i * 256] = v[i] * inv;
}

// ============================================================
// Kernel 2: compose fused weights
//   Wf[k][j]     = sum_d Wp[k][d] * W1[d][j]        (j <  64)
//   Wf[k][64+j]  = sum_d Wp[k][d] * W1[64+d][j]     (j <  64)
//   bf[j]        = sum_k bp[k] * W1[k][j]
//   bf[64+j]     = sum_k bp[k] * W1[64+k][j] + b1[j]
// grid 8 blocks, each does 8 rows of Wf
// ============================================================
__global__ void __launch_bounds__(256) compose_kernel(
    const float* __restrict__ Wp, const float* __restrict__ bp,
    const float* __restrict__ W1, const float* __restrict__ b1)
{
    __shared__ float sW1[128 * 64];   // 32 KB
    __shared__ float sWp[8 * 64];
    int tid = threadIdx.x;
    int k0 = blockIdx.x * 8;
    for (int i = tid; i < 8192; i += 256) sW1[i] = W1[i];
    for (int i = tid; i < 512; i += 256) sWp[i] = Wp[k0 * 64 + i];
    __syncthreads();

    int r = tid >> 5;             // local row 0..7
    int jq = (tid & 31) << 2;     // col group 0..124
    const float* base = (jq < 64) ? (sW1 + jq) : (sW1 + 64 * 64 + (jq - 64));
    float4 acc = make_float4(0.f, 0.f, 0.f, 0.f);
    const float* wr = sWp + r * 64;
#pragma unroll
    for (int d = 0; d < 64; d++) {
        float w = wr[d];
        float4 c = *(const float4*)(base + d * 64);
        acc.x = fmaf(w, c.x, acc.x);
        acc.y = fmaf(w, c.y, acc.y);
        acc.z = fmaf(w, c.z, acc.z);
        acc.w = fmaf(w, c.w, acc.w);
    }
    *(float4*)(g_Wf + (k0 + r) * 128 + jq) = acc;

    // bias (block 0, first 128 threads)
    if (blockIdx.x == 0 && tid < 128) {
        int j = tid;
        float acc_b = 0.f;
        const float* col = (j < 64) ? (sW1 + j) : (sW1 + 64 * 64 + (j - 64));
#pragma unroll
        for (int k = 0; k < 64; k++) acc_b += bp[k] * col[k * 64];
        if (j >= 64) acc_b += b1[j - 64];
        g_bf[j] = acc_b;
    }
}

// ============================================================
// Kernel 3: ps = es @ Wf[:, :64] + bf[:64]
//           ptb = es @ Wf[:, 64:] + bf[64:]
// ============================================================
__global__ void __launch_bounds__(256) pspt_kernel(const float* __restrict__ es)
{
    __shared__ float sW[64 * 128];   // 32 KB
    __shared__ float sE[16 * 64];
    int tid = threadIdx.x;
    int row0 = blockIdx.x * 16;
    for (int i = tid; i < 8192; i += 256) sW[i] = g_Wf[i];
    for (int i = tid; i < 1024; i += 256) sE[i] = es[row0 * 64 + i];
    __syncthreads();

    int r = tid >> 4;
    int q = (tid & 15) << 2;
    float4 aps = *(const float4*)(g_bf + q);
    float4 apt = *(const float4*)(g_bf + 64 + q);
    const float* er = sE + r * 64;
#pragma unroll
    for (int k = 0; k < 64; k++) {
        float e = er[k];
        float4 wa = *(const float4*)(sW + k * 128 + q);
        float4 wb = *(const float4*)(sW + k * 128 + 64 + q);
        aps.x = fmaf(e, wa.x, aps.x);
        aps.y = fmaf(e, wa.y, aps.y);
        aps.z = fmaf(e, wa.z, aps.z);
        aps.w = fmaf(e, wa.w, aps.w);
        apt.x = fmaf(e, wb.x, apt.x);
        apt.y = fmaf(e, wb.y, apt.y);
        apt.z = fmaf(e, wb.z, apt.z);
        apt.w = fmaf(e, wb.w, apt.w);
    }
    *(float4*)(g_ps  + (row0 + r) * 64 + q) = aps;
    *(float4*)(g_ptb + (row0 + r) * 64 + q) = apt;
}

// ============================================================
// Kernel 4 (hot): hpart[c,b,t,:] = sum_{s in chunk c} A[t,s] *
//                 relu(ps[b,s,:] + ptb[b,t,:])      — packed f32x2
// grid (SCHUNKS, N/TT, B), 256 threads
// ============================================================
__global__ void __launch_bounds__(256, 5) msg_agg_kernel(const float* __restrict__ A)
{
    __shared__ float sP[SC * 64];    // 16 KB ps tile
    __shared__ float2 sA[TT * SC];   // 16 KB duplicated-packed A tile
    int b  = blockIdx.z;
    int t0 = blockIdx.y * TT;
    int s0 = blockIdx.x * SC;
    int tid = threadIdx.x;

    {
        const float4* gp = (const float4*)(g_ps + (b * Nn + s0) * Dn);
        float4* sp4 = (float4*)sP;
#pragma unroll
        for (int i = 0; i < (SC * 16) / 256; i++)
            sp4[tid + i * 256] = gp[tid + i * 256];
#pragma unroll
        for (int i = tid; i < TT * SC; i += 256) {
            int tl = i >> 6;          // / SC (=64)
            int sl = i & (SC - 1);
            float a = A[(t0 + tl) * Nn + s0 + sl];
            sA[i] = make_float2(a, a);
        }
    }
    __syncthreads();

    int q  = (tid & 15) << 2;
    int tg = tid >> 4;
    int ta = t0 + tg * 2;
    float4 c0 = *(const float4*)(g_ptb + (b * Nn + ta) * Dn + q);
    float4 c1 = *(const float4*)(g_ptb + (b * Nn + ta + 1) * Dn + q);
    u64t c0a = pack2(c0.x, c0.y), c0b = pack2(c0.z, c0.w);
    u64t c1a = pack2(c1.x, c1.y), c1b = pack2(c1.z, c1.w);
    u64t acc0a = 0, acc0b = 0, acc1a = 0, acc1b = 0;
    const float4* p4 = ((const float4*)sP) + (q >> 2);
    const u64t* a0 = (const u64t*)(sA + (tg * 2) * SC);
    const u64t* a1 = a0 + SC;

#pragma unroll 4
    for (int s = 0; s < SC; s++) {
        float4 p = p4[s * 16];
        u64t pa = pack2(p.x, p.y);
        u64t pb = pack2(p.z, p.w);
        u64t aa = a0[s];
        u64t ab = a1[s];
        acc0a = fma2(aa, relu2(add2(pa, c0a)), acc0a);
        acc0b = fma2(aa, relu2(add2(pb, c0b)), acc0b);
        acc1a = fma2(ab, relu2(add2(pa, c1a)), acc1a);
        acc1b = fma2(ab, relu2(add2(pb, c1b)), acc1b);
    }

    int c = blockIdx.x;
    float* hp = g_hpart + (size_t)(c * Bn + b) * Nn * Dn;
    float4 o0, o1;
    unpack2(acc0a, o0.x, o0.y); unpack2(acc0b, o0.z, o0.w);
    unpack2(acc1a, o1.x, o1.y); unpack2(acc1b, o1.z, o1.w);
    *(float4*)(hp + (size_t)ta * Dn + q)       = o0;
    *(float4*)(hp + (size_t)(ta + 1) * Dn + q) = o1;
}

// ============================================================
// Kernel 5: hbar = sum_c hpart;  next_state = es + hbar @ W2 + b2
// ============================================================
__global__ void __launch_bounds__(256) out_kernel(
    const float* __restrict__ es, const float* __restrict__ W2,
    const float* __restrict__ b2, float* __restrict__ ns)
{
    __shared__ float sW[64 * 64];
    __shared__ float sH[16 * 64];
    int tid = threadIdx.x;
    int row0 = blockIdx.x * 16;
    for (int i = tid; i < 4096; i += 256) sW[i] = W2[i];
    for (int i = tid; i < 1024; i += 256) {
        int gr = row0 + (i >> 6);
        int d  = i & 63;
        float h = 0.f;
#pragma unroll
        for (int c = 0; c < SCHUNKS; c++)
            h += g_hpart[((size_t)c * Bn * Nn + gr) * Dn + d];
        sH[i] = h;
    }
    __syncthreads();

    int r = tid >> 4;
    int q = (tid & 15) << 2;
    float4 acc = *(const float4*)(b2 + q);
    const float* hr = sH + r * 64;
#pragma unroll
    for (int k = 0; k < 64; k++) {
        float h = hr[k];
        float4 w = *(const float4*)(sW + k * 64 + q);
        acc.x = fmaf(h, w.x, acc.x);
        acc.y = fmaf(h, w.y, acc.y);
        acc.z = fmaf(h, w.z, acc.z);
        acc.w = fmaf(h, w.w, acc.w);
    }
    float4 e = *(const float4*)(es + (row0 + r) * 64 + q);
    acc.x += e.x; acc.y += e.y; acc.z += e.z; acc.w += e.w;
    *(float4*)(ns + (row0 + r) * 64 + q) = acc;
}

// ============================================================
extern "C" void kernel_launch(void* const* d_in, const int* in_sizes, int n_in,
                              void* d_out, int out_size)
{
    const float* es = (const float*)d_in[0];
    const float* u  = (const float*)d_in[1];
    const float* Wp = (const float*)d_in[2];
    const float* bp = (const float*)d_in[3];
    const float* el = (const float*)d_in[4];
    const float* W1 = (const float*)d_in[5];
    const float* b1 = (const float*)d_in[6];
    const float* W2 = (const float*)d_in[7];
    const float* b2 = (const float*)d_in[8];

    float* outNS = (float*)d_out;                 // next_state [B,N,D]
    float* outA  = outNS + Bn * Nn * Dn;          // A [N,N]

    gumbel_softmax_kernel<<<Nn, 256>>>(u, el, outA);
    compose_kernel<<<8, 256>>>(Wp, bp, W1, b1);
    pspt_kernel<<<(Bn * Nn) / 16, 256>>>(es);
    msg_agg_kernel<<<dim3(SCHUNKS, Nn / TT, Bn), 256>>>(outA);
    out_kernel<<<(Bn * Nn) / 16, 256>>>(es, W2, b2, outNS);
}

// round 3
// speedup vs baseline: 1.2654x; 1.0576x over previous
#include <cuda_runtime.h>
#include <math.h>

#define Bn 2
#define Nn 1024
#define Dn 64
#define SCHUNKS 16          // s-dimension split for msg_agg
#define TT 64               // t-tile per block in msg_agg
#define SC (Nn / SCHUNKS)   // 64 s per block
#define SA_STRIDE 68        // padded [s][t] stride (17 float4s) — conflict-safe, 16B aligned

typedef unsigned long long u64t;

// -------- scratch (no malloc allowed) --------
__device__ float g_ps[Bn * Nn * Dn];
__device__ float g_ptb[Bn * Nn * Dn];
__device__ float g_hpart[SCHUNKS * Bn * Nn * Dn];

// ---------- packed f32x2 helpers ----------
__device__ __forceinline__ u64t pack2(float lo, float hi) {
    u64t r;
    asm("mov.b64 %0, {%1, %2};" : "=l"(r) : "f"(lo), "f"(hi));
    return r;
}
__device__ __forceinline__ void unpack2(u64t v, float& lo, float& hi) {
    asm("mov.b64 {%0, %1}, %2;" : "=f"(lo), "=f"(hi) : "l"(v));
}
__device__ __forceinline__ u64t add2(u64t a, u64t b) {
    u64t d;
    asm("add.rn.f32x2 %0, %1, %2;" : "=l"(d) : "l"(a), "l"(b));
    return d;
}
__device__ __forceinline__ u64t fma2(u64t a, u64t b, u64t c) {
    u64t d;
    asm("fma.rn.f32x2 %0, %1, %2, %3;" : "=l"(d) : "l"(a), "l"(b), "l"(c));
    return d;
}
__device__ __forceinline__ u64t relu2(u64t x) {
    u64t r;
    asm("{\n\t"
        ".reg .f32 lo, hi;\n\t"
        "mov.b64 {lo, hi}, %1;\n\t"
        "max.f32 lo, lo, 0f00000000;\n\t"
        "max.f32 hi, hi, 0f00000000;\n\t"
        "mov.b64 %0, {lo, hi};\n\t"
        "}" : "=l"(r) : "l"(x));
    return r;
}

// ============================================================
// K1 fused: blocks [0,128)  : pspt-direct (proj then ps/ptb, in-smem chain)
//           blocks [128,1152): gumbel softmax row (bx-128)
// ============================================================
__global__ void __launch_bounds__(256) k1_fused_kernel(
    const float* __restrict__ es, const float* __restrict__ u,
    const float* __restrict__ Wp, const float* __restrict__ bp,
    const float* __restrict__ el, const float* __restrict__ W1,
    const float* __restrict__ b1, float* __restrict__ A)
{
    __shared__ __align__(16) float sm[14336];   // 56 KB
    int tid = threadIdx.x;

    if (blockIdx.x < 128) {
        // ---------------- pspt-direct ----------------
        float* sW1 = sm;            // [128][64]
        float* sWp = sm + 8192;     // [64][64]
        float* sE  = sm + 12288;    // [16][64]
        float* sPr = sm + 13312;    // [16][64]
        int row0 = blockIdx.x * 16; // global row in [0, B*N)

        for (int i = tid; i < 8192; i += 256) sW1[i] = W1[i];
        for (int i = tid; i < 4096; i += 256) sWp[i] = Wp[i];
        for (int i = tid; i < 1024; i += 256) sE[i] = es[row0 * 64 + i];
        __syncthreads();

        int r = tid >> 4;
        int q = (tid & 15) << 2;

        // proj = es @ Wp + bp
        {
            float4 acc = *(const float4*)(bp + q);
            const float* er = sE + r * 64;
#pragma unroll
            for (int k = 0; k < 64; k++) {
                float e = er[k];
                float4 w = *(const float4*)(sWp + k * 64 + q);
                acc.x = fmaf(e, w.x, acc.x);
                acc.y = fmaf(e, w.y, acc.y);
                acc.z = fmaf(e, w.z, acc.z);
                acc.w = fmaf(e, w.w, acc.w);
            }
            *(float4*)(sPr + r * 64 + q) = acc;
        }
        __syncthreads();

        // ps = proj @ W1[:64], ptb = proj @ W1[64:] + b1
        {
            float4 aps = make_float4(0.f, 0.f, 0.f, 0.f);
            float4 apt = *(const float4*)(b1 + q);
            const float* pr = sPr + r * 64;
#pragma unroll
            for (int k = 0; k < 64; k++) {
                float p = pr[k];
                float4 wa = *(const float4*)(sW1 + k * 64 + q);
                float4 wb = *(const float4*)(sW1 + (64 + k) * 64 + q);
                aps.x = fmaf(p, wa.x, aps.x);
                aps.y = fmaf(p, wa.y, aps.y);
                aps.z = fmaf(p, wa.z, aps.z);
                aps.w = fmaf(p, wa.w, aps.w);
                apt.x = fmaf(p, wb.x, apt.x);
                apt.y = fmaf(p, wb.y, apt.y);
                apt.z = fmaf(p, wb.z, apt.z);
                apt.w = fmaf(p, wb.w, apt.w);
            }
            *(float4*)(g_ps  + (row0 + r) * 64 + q) = aps;
            *(float4*)(g_ptb + (row0 + r) * 64 + q) = apt;
        }
    } else {
        // ---------------- gumbel softmax ----------------
        float* redm = sm;
        float* reds = sm + 8;
        int t = blockIdx.x - 128;
        const float* ur = u + t * Nn;
        const float* er = el + t * Nn;

        float v[4];
        float mx = -3.4e38f;
#pragma unroll
        for (int i = 0; i < 4; i++) {
            int s = tid + i * 256;
            float g = -__logf(-__logf(ur[s] + 1e-9f) + 1e-9f);
            float m = (s == t) ? -1e9f : er[s];
            float L = (m + g) * 2.0f;   // / tau, tau = 0.5
            v[i] = L;
            mx = fmaxf(mx, L);
        }
#pragma unroll
        for (int o = 16; o; o >>= 1) mx = fmaxf(mx, __shfl_xor_sync(0xffffffffu, mx, o));
        if ((tid & 31) == 0) redm[tid >> 5] = mx;
        __syncthreads();
        float bm = redm[0];
#pragma unroll
        for (int i = 1; i < 8; i++) bm = fmaxf(bm, redm[i]);

        float sum = 0.f;
#pragma unroll
        for (int i = 0; i < 4; i++) { v[i] = __expf(v[i] - bm); sum += v[i]; }
#pragma unroll
        for (int o = 16; o; o >>= 1) sum += __shfl_xor_sync(0xffffffffu, sum, o);
        if ((tid & 31) == 0) reds[tid >> 5] = sum;
        __syncthreads();
        float bs = reds[0];
#pragma unroll
        for (int i = 1; i < 8; i++) bs += reds[i];
        float inv = 1.0f / bs;

#pragma unroll
        for (int i = 0; i < 4; i++)
            A[t * Nn + tid + i * 256] = v[i] * inv;
    }
}

// ============================================================
// K2 (hot): hpart[c,b,t,:] = sum_{s in chunk c} A[t,s]*relu(ps[b,s,:]+ptb[b,t,:])
// grid (SCHUNKS, Nn/TT, Bn), 256 threads
// thread: tg = tid>>4 handles t = t0 + tg*4 + {0..3};  q = tid&15 handles 4 d
// ============================================================
__global__ void __launch_bounds__(256, 4) msg_agg_kernel(const float* __restrict__ A)
{
    __shared__ __align__(16) float sP[SC * 64];          // 16 KB [s][d]
    __shared__ __align__(16) float sA[SC * SA_STRIDE];   // 17.4 KB [s][t], padded
    int b  = blockIdx.z;
    int t0 = blockIdx.y * TT;
    int s0 = blockIdx.x * SC;
    int tid = threadIdx.x;

    {
        const float4* gp = (const float4*)(g_ps + (b * Nn + s0) * Dn);
        float4* sp4 = (float4*)sP;
#pragma unroll
        for (int i = 0; i < (SC * 16) / 256; i++)
            sp4[tid + i * 256] = gp[tid + i * 256];
#pragma unroll
        for (int k = 0; k < (TT * SC) / 256; k++) {
            int i = tid + k * 256;
            int sl = i & (SC - 1);
            int tl = i >> 6;           // / SC(=64)
            sA[sl * SA_STRIDE + tl] = A[(t0 + tl) * Nn + s0 + sl];
        }
    }
    __syncthreads();

    int q4 = (tid & 15) << 2;
    int tg = tid >> 4;
    int ta = t0 + tg * 4;

    // per-t constants c = ptb[b, ta+i, q4..q4+3] as f32x2 pairs
    u64t c[8];
#pragma unroll
    for (int i = 0; i < 4; i++) {
        float4 cv = *(const float4*)(g_ptb + (b * Nn + ta + i) * Dn + q4);
        c[2 * i]     = pack2(cv.x, cv.y);
        c[2 * i + 1] = pack2(cv.z, cv.w);
    }
    u64t acc[8];
#pragma unroll
    for (int i = 0; i < 8; i++) acc[i] = 0;

    const float4* pbase = ((const float4*)sP) + (tid & 15);  // [s*16]
    const float4* abase = ((const float4*)sA) + tg;          // [s*17]

#pragma unroll 8
    for (int s = 0; s < SC; s++) {
        float4 p  = pbase[s * 16];
        float4 av = abase[s * (SA_STRIDE / 4)];
        u64t pa = pack2(p.x, p.y);
        u64t pb = pack2(p.z, p.w);
        u64t a0 = pack2(av.x, av.x);
        u64t a1 = pack2(av.y, av.y);
        u64t a2 = pack2(av.z, av.z);
        u64t a3 = pack2(av.w, av.w);
        acc[0] = fma2(a0, relu2(add2(pa, c[0])), acc[0]);
        acc[1] = fma2(a0, relu2(add2(pb, c[1])), acc[1]);
        acc[2] = fma2(a1, relu2(add2(pa, c[2])), acc[2]);
        acc[3] = fma2(a1, relu2(add2(pb, c[3])), acc[3]);
        acc[4] = fma2(a2, relu2(add2(pa, c[4])), acc[4]);
        acc[5] = fma2(a2, relu2(add2(pb, c[5])), acc[5]);
        acc[6] = fma2(a3, relu2(add2(pa, c[6])), acc[6]);
        acc[7] = fma2(a3, relu2(add2(pb, c[7])), acc[7]);
    }

    int cidx = blockIdx.x;
    float* hp = g_hpart + ((size_t)(cidx * Bn + b) * Nn + ta) * Dn + q4;
#pragma unroll
    for (int i = 0; i < 4; i++) {
        float4 o;
        unpack2(acc[2 * i],     o.x, o.y);
        unpack2(acc[2 * i + 1], o.z, o.w);
        *(float4*)(hp + (size_t)i * Dn) = o;
    }
}

// ============================================================
// K3: hbar = sum_c hpart;  next_state = es + hbar @ W2 + b2
// 128 blocks x 256 thr, 16 rows per block
// ============================================================
__global__ void __launch_bounds__(256) out_kernel(
    const float* __restrict__ es, const float* __restrict__ W2,
    const float* __restrict__ b2, float* __restrict__ ns)
{
    __shared__ __align__(16) float sW[64 * 64];
    __shared__ __align__(16) float sH[16 * 64];
    int tid = threadIdx.x;
    int row0 = blockIdx.x * 16;    // global row in [0, B*N)

    for (int i = tid; i < 4096; i += 256) sW[i] = W2[i];
    {
        // each thread owns one float4 of sH: 16 rows x 16 float4 = 256
        int r  = tid >> 4;
        int f4 = tid & 15;
        size_t base = ((size_t)(row0 + r)) * 16 + f4;   // float4 index into [B*N][16]
        float4 acc = make_float4(0.f, 0.f, 0.f, 0.f);
#pragma unroll
        for (int cc = 0; cc < SCHUNKS; cc++) {
            float4 v = ((const float4*)g_hpart)[(size_t)cc * (Bn * Nn * 16) + base];
            acc.x += v.x; acc.y += v.y; acc.z += v.z; acc.w += v.w;
        }
        ((float4*)sH)[tid] = acc;
    }
    __syncthreads();

    int r = tid >> 4;
    int q = (tid & 15) << 2;
    float4 acc = *(const float4*)(b2 + q);
    const float* hr = sH + r * 64;
#pragma unroll
    for (int k = 0; k < 64; k++) {
        float h = hr[k];
        float4 w = *(const float4*)(sW + k * 64 + q);
        acc.x = fmaf(h, w.x, acc.x);
        acc.y = fmaf(h, w.y, acc.y);
        acc.z = fmaf(h, w.z, acc.z);
        acc.w = fmaf(h, w.w, acc.w);
    }
    float4 e = *(const float4*)(es + (row0 + r) * 64 + q);
    acc.x += e.x; acc.y += e.y; acc.z += e.z; acc.w += e.w;
    *(float4*)(ns + (row0 + r) * 64 + q) = acc;
}

// ============================================================
extern "C" void kernel_launch(void* const* d_in, const int* in_sizes, int n_in,
                              void* d_out, int out_size)
{
    const float* es = (const float*)d_in[0];
    const float* u  = (const float*)d_in[1];
    const float* Wp = (const float*)d_in[2];
    const float* bp = (const float*)d_in[3];
    const float* el = (const float*)d_in[4];
    const float* W1 = (const float*)d_in[5];
    const float* b1 = (const float*)d_in[6];
    const float* W2 = (const float*)d_in[7];
    const float* b2 = (const float*)d_in[8];

    float* outNS = (float*)d_out;                 // next_state [B,N,D]
    float* outA  = outNS + Bn * Nn * Dn;          // A [N,N]

    k1_fused_kernel<<<128 + Nn, 256>>>(es, u, Wp, bp, el, W1, b1, outA);
    msg_agg_kernel<<<dim3(SCHUNKS, Nn / TT, Bn), 256>>>(outA);
    out_kernel<<<(Bn * Nn) / 16, 256>>>(es, W2, b2, outNS);
}